// round 7
// baseline (speedup 1.0000x reference)
#include <cuda_runtime.h>
#include <cstdint>
#include <math.h>

#define NEGBIG -3.0e38f

// ---------------- scratch (device globals; no allocation allowed) ------------
__device__ float g_H[2048 * 576];    // cols 0:192 relu(fc1)=H0, 192:384 H1, 384:576 H2
__device__ float g_giC[2048 * 576];  // precomputed x@Wih_c^T + bih_c for current layer
__device__ float g_ghP[2048 * 576];  // precomputed x@Whh_p^T + bhh_p
__device__ float g_t0[2048 * 192];
__device__ float g_t1[2048 * 192];

// ---------------- generic fp32 tiled GEMM: C = act(A*B(+T) + bias) -----------
template <int BT, int RELU>
__global__ void __launch_bounds__(256) gemm_kernel(
    const float* __restrict__ A, int lda,
    const float* __restrict__ B, const float* __restrict__ bias,
    float* __restrict__ C, int ldc, int M, int N, int K)
{
    __shared__ float As[64][33];
    __shared__ float Bs[32][65];
    const int tid = threadIdx.x;
    const int tx = tid & 15, ty = tid >> 4;
    const int bx = blockIdx.x, by = blockIdx.y;
    const int kl = tid & 31, rl = tid >> 5;
    float acc[4][4] = {};
    for (int k0 = 0; k0 < K; k0 += 32) {
        #pragma unroll
        for (int mm = 0; mm < 64; mm += 8)
            As[mm + rl][kl] = A[(size_t)(by * 64 + mm + rl) * lda + k0 + kl];
        if (BT) {
            #pragma unroll
            for (int nn = 0; nn < 64; nn += 8)
                Bs[kl][nn + rl] = B[(size_t)(bx * 64 + nn + rl) * K + k0 + kl];
        } else {
            const int nc = tid & 63, kr = tid >> 6;
            #pragma unroll
            for (int kk = 0; kk < 32; kk += 4)
                Bs[kk + kr][nc] = B[(size_t)(k0 + kk + kr) * N + bx * 64 + nc];
        }
        __syncthreads();
        #pragma unroll
        for (int kk = 0; kk < 32; kk++) {
            float a[4], bb[4];
            #pragma unroll
            for (int i = 0; i < 4; i++) a[i] = As[ty * 4 + i][kk];
            #pragma unroll
            for (int j = 0; j < 4; j++) bb[j] = Bs[kk][tx * 4 + j];
            #pragma unroll
            for (int i = 0; i < 4; i++)
                #pragma unroll
                for (int j = 0; j < 4; j++)
                    acc[i][j] = fmaf(a[i], bb[j], acc[i][j]);
        }
        __syncthreads();
    }
    #pragma unroll
    for (int i = 0; i < 4; i++) {
        const int row = by * 64 + ty * 4 + i;
        #pragma unroll
        for (int j = 0; j < 4; j++) {
            const int col = bx * 64 + tx * 4 + j;
            float v = acc[i][j] + bias[col];
            if (RELU) v = v > 0.f ? v : 0.f;
            C[(size_t)row * ldc + col] = v;
        }
    }
}

// ---------------- sequential scan: one 8-CTA cluster per batch ---------------
struct ScanArgs {
    const float* Hl;     // layer input, row stride 576
    const float* adj;    // (8,256,256)
    const float* smask;  // (8,256,256)
    const float* wk;     // (192,)
    const float* wr0;    // (192,192)
    const float* wr1;    // (192,192)
    const float* whhC;   // (576,192)
    const float* wihP;   // (576,192)
    const float* bhhC;   // (576,)
    const float* biP;    // (576,)
    const float* giC;    // (2048,576)
    const float* ghP;    // (2048,576)
    float* Hout;         // g_H + (l+1)*192, row stride 576
    float* attnL;        // attn + l*65536; batch stride 131072, row stride 256
};

struct SmemScan {
    float V0[256][25];   // pitch 25 -> conflict-free column reads
    float V1[256][25];
    float Ksc[256];
    float Attn[256];
    float Sm[256];
    float Adj[256];
    alignas(16) float Mfull[192];
    alignas(16) float Hnew[192];
    float X24[24];
    float giCs[72];
    float ghPs[72];
    float Gres[144];
    float Gbias[144];
    alignas(8) unsigned long long mbM;   // Mfull-exchange mbarrier (count 192)
};

__device__ __forceinline__ void st_remote(float* p, unsigned rank, float v) {
    unsigned laddr = (unsigned)__cvta_generic_to_shared(p);
    unsigned raddr;
    asm volatile("mapa.shared::cluster.u32 %0, %1, %2;" : "=r"(raddr) : "r"(laddr), "r"(rank));
    asm volatile("st.shared::cluster.f32 [%0], %1;" :: "r"(raddr), "f"(v) : "memory");
}

__device__ __forceinline__ void mbar_arrive_remote(void* mb, unsigned rank) {
    unsigned laddr = (unsigned)__cvta_generic_to_shared(mb);
    asm volatile(
        "{\n\t.reg .b32 r;\n\t"
        "mapa.shared::cluster.u32 r, %0, %1;\n\t"
        "mbarrier.arrive.release.cluster.shared::cluster.b64 _, [r];\n\t}"
        :: "r"(laddr), "r"(rank) : "memory");
}

__device__ __forceinline__ void mbar_wait(void* mb, unsigned parity) {
    unsigned addr = (unsigned)__cvta_generic_to_shared(mb);
    asm volatile(
        "{\n\t.reg .pred P;\n\t"
        "WL%=:\n\t"
        "mbarrier.try_wait.parity.acquire.cluster.shared::cta.b64 P, [%0], %1, 0x989680;\n\t"
        "@P bra WD%=;\n\t"
        "bra WL%=;\n\t"
        "WD%=:\n\t}"
        :: "r"(addr), "r"(parity) : "memory");
}

__device__ __forceinline__ void mbar_init(void* mb, unsigned count) {
    unsigned addr = (unsigned)__cvta_generic_to_shared(mb);
    asm volatile("mbarrier.init.shared.b64 [%0], %1;" :: "r"(addr), "r"(count) : "memory");
}

__device__ __forceinline__ void cluster_sync_all() {
    asm volatile("barrier.cluster.arrive.aligned;" ::: "memory");
    asm volatile("barrier.cluster.wait.aligned;" ::: "memory");
}

__device__ __forceinline__ float sigmf(float x) { return 1.f / (1.f + __expf(-x)); }

__global__ void __cluster_dims__(8, 1, 1) __launch_bounds__(512, 1) scan_kernel(ScanArgs A)
{
    extern __shared__ char smem_raw[];
    SmemScan& S = *reinterpret_cast<SmemScan*>(smem_raw);
    const int tid = threadIdx.x, warp = tid >> 5, lane = tid & 31;
    const int crank = blockIdx.x & 7, b = blockIdx.x >> 3, d0 = crank * 24;
    const int t2 = tid - 288;   // service-relative id (warps 9-15), gate warps: t2<0

    // ---- one-time init ----
    for (int idx = tid; idx < 256 * 25; idx += 512) {
        (&S.V0[0][0])[idx] = 0.f;
        (&S.V1[0][0])[idx] = 0.f;
    }
    if (tid < 256) S.Ksc[tid] = 0.f;
    if (tid < 192) { S.Mfull[tid] = 0.f; S.Hnew[tid] = 0.f; }
    if (tid < 144) {
        int oo = (tid < 72) ? tid : tid - 72;
        int g = oo / 24, d = oo % 24;
        S.Gbias[tid] = (tid < 72) ? A.bhhC[g * 192 + d0 + d] : A.biP[g * 192 + d0 + d];
    }
    if (tid == 0) mbar_init(&S.mbM, 192);

    // unified register weight array: gate threads use [0..95], service use [0..47]
    float wreg[96];
    if (tid < 288) {
        // gate warps: thread = 2*o + p (o in 0..143, p in 0..1), 96 k-values each
        const int o = tid >> 1, p = tid & 1;
        const float* W;
        int rowi;
        if (o < 72)  { W = A.whhC; int g = o / 24, d = o % 24; rowi = g * 192 + d0 + d; }
        else         { int oo = o - 72; W = A.wihP; int g = oo / 24, d = oo % 24; rowi = g * 192 + d0 + d; }
        const float* src = W + (size_t)rowi * 192 + p * 96;
        #pragma unroll
        for (int k4 = 0; k4 < 24; k4++) {
            float4 v = *reinterpret_cast<const float4*>(src + 4 * k4);
            wreg[4 * k4 + 0] = v.x; wreg[4 * k4 + 1] = v.y;
            wreg[4 * k4 + 2] = v.z; wreg[4 * k4 + 3] = v.w;
        }
    } else {
        // service warps: thread = 4*o + p (o in 0..48 clamped, p in 0..3), 48 k-values
        const int o = t2 >> 2, p = t2 & 3;
        const int oc = (o < 49) ? o : 48;   // clamp: t2 >= 196 loads wk row (valid mem)
        const float* src;
        if (oc < 24)      src = A.wr0 + (size_t)(d0 + oc) * 192;
        else if (oc < 48) src = A.wr1 + (size_t)(d0 + oc - 24) * 192;
        else              src = A.wk;
        src += p * 48;
        #pragma unroll
        for (int k4 = 0; k4 < 12; k4++) {
            float4 v = *reinterpret_cast<const float4*>(src + 4 * k4);
            wreg[4 * k4 + 0] = v.x; wreg[4 * k4 + 1] = v.y;
            wreg[4 * k4 + 2] = v.z; wreg[4 * k4 + 3] = v.w;
        }
    }
    __syncthreads();
    cluster_sync_all();   // smem init + mbarrier init visible cluster-wide

    const size_t rb = (size_t)b * 256;
    for (int i = 0; i < 256; i++) {
        const size_t row = rb + i;
        float* attnRow = A.attnL + (size_t)b * 131072 + (size_t)i * 256;

        // ---- prefetch step-local data (service warps; no shfl here) ----
        if (t2 >= 0) {
            if (t2 < 224) {
                S.Sm[t2]  = A.smask[row * 256 + t2];
                S.Adj[t2] = A.adj[row * 256 + t2];
            }
            if (t2 < 32) {
                S.Sm[224 + t2]  = A.smask[row * 256 + 224 + t2];
                S.Adj[224 + t2] = A.adj[row * 256 + 224 + t2];
            }
            if (t2 < 72)       S.giCs[t2] = A.giC[row * 576 + (t2 / 24) * 192 + d0 + (t2 % 24)];
            else if (t2 < 144) { int u = t2 - 72; S.ghPs[u] = A.ghP[row * 576 + (u / 24) * 192 + d0 + (u % 24)]; }
            else if (t2 < 168) S.X24[t2 - 144] = A.Hl[row * 576 + d0 + (t2 - 144)];
        }

        // ---- fold prev Hnew into V0/V1/Ksc. ALL 224 service lanes execute the
        //      body (shfl participation!); only o<49 && p==0 stores. ----
        if (i > 0 && t2 >= 0) {
            const int o = t2 >> 2, p = t2 & 3;
            float s0 = 0.f, s1 = 0.f, s2 = 0.f, s3 = 0.f;
            #pragma unroll
            for (int k4 = 0; k4 < 12; k4 += 4) {
                #pragma unroll
                for (int u = 0; u < 4; u++) {
                    float4 h4 = *reinterpret_cast<const float4*>(&S.Hnew[p * 48 + 4 * (k4 + u)]);
                    s0 = fmaf(h4.x, wreg[4 * (k4 + u) + 0], s0);
                    s1 = fmaf(h4.y, wreg[4 * (k4 + u) + 1], s1);
                    s2 = fmaf(h4.z, wreg[4 * (k4 + u) + 2], s2);
                    s3 = fmaf(h4.w, wreg[4 * (k4 + u) + 3], s3);
                }
            }
            float s = (s0 + s1) + (s2 + s3);
            s += __shfl_xor_sync(0xffffffffu, s, 1);
            s += __shfl_xor_sync(0xffffffffu, s, 2);
            if (p == 0 && o < 49) {
                if (o < 24)      S.V0[i - 1][o] = s;
                else if (o < 48) S.V1[i - 1][o - 24] = s;
                else             S.Ksc[i - 1] = s;
            }
        }
        __syncthreads();   // Ksc/V/Sm/Adj/giCs/ghPs/X24 ready

        // ---- masked softmax entirely in warp 9 (wq/gat_b terms cancel) ----
        if (i > 0) {
            if (warp == 9) {
                float a[8];
                #pragma unroll
                for (int q = 0; q < 8; q++) {
                    int j = lane + 32 * q;
                    bool msk = (j < i) && (S.Adj[j] > 0.5f);
                    a[q] = msk ? S.Ksc[j] : NEGBIG;
                }
                float m = a[0];
                #pragma unroll
                for (int q = 1; q < 8; q++) m = fmaxf(m, a[q]);
                #pragma unroll
                for (int o = 16; o; o >>= 1) m = fmaxf(m, __shfl_xor_sync(0xffffffffu, m, o));
                float e[8], su = 0.f;
                #pragma unroll
                for (int q = 0; q < 8; q++) { e[q] = __expf(a[q] - m); su += e[q]; }
                #pragma unroll
                for (int o = 16; o; o >>= 1) su += __shfl_xor_sync(0xffffffffu, su, o);
                float inv = 1.f / su;
                float mine = 0.f;
                #pragma unroll
                for (int q = 0; q < 8; q++) {
                    float v = e[q] * inv;
                    S.Attn[lane + 32 * q] = v;
                    if (q == crank) mine = v;
                }
                attnRow[crank * 32 + lane] = mine;   // this CTA's 32 output cols
            }
        } else {
            if (warp == 9) attnRow[crank * 32 + lane] = 0.f;
        }
        __syncthreads();   // Attn ready

        // ---- M slice (7 service warps), scatter + mbarrier arrive inline ----
        if (i > 0 && t2 >= 0) {
            const int w2 = warp - 9;
            for (int dd = w2; dd < 24; dd += 7) {
                float s = 0.f;
                for (int j = lane; j < i; j += 32) {
                    float v1 = S.V1[j][dd];
                    float vr = fmaf(S.V0[j][dd] - v1, S.Sm[j], v1);
                    s = fmaf(S.Attn[j], vr, s);
                }
                #pragma unroll
                for (int o = 16; o; o >>= 1) s += __shfl_xor_sync(0xffffffffu, s, o);
                if (lane < 8) {
                    st_remote(&S.Mfull[d0 + dd], lane, s);
                    mbar_arrive_remote(&S.mbM, lane);   // release: orders the store
                }
            }
        }
        // wait for all 192 M contributions (i-th completion -> parity (i-1)&1)
        if (i > 0) mbar_wait(&S.mbM, (unsigned)((i - 1) & 1));

        // ---- gates: register-weight FMA (warps 0-8) ----
        if (tid < 288) {
            const int o = tid >> 1, p = tid & 1;
            float s0 = 0.f, s1 = 0.f, s2 = 0.f, s3 = 0.f;
            #pragma unroll
            for (int kk = 0; kk < 24; kk++) {
                float4 m4 = *reinterpret_cast<const float4*>(&S.Mfull[p * 96 + 4 * kk]);
                s0 = fmaf(m4.x, wreg[4 * kk + 0], s0);
                s1 = fmaf(m4.y, wreg[4 * kk + 1], s1);
                s2 = fmaf(m4.z, wreg[4 * kk + 2], s2);
                s3 = fmaf(m4.w, wreg[4 * kk + 3], s3);
            }
            float s = (s0 + s1) + (s2 + s3);
            s += __shfl_xor_sync(0xffffffffu, s, 1);
            if (p == 0) S.Gres[o] = s + S.Gbias[o];
        }
        __syncthreads();   // Gres ready

        // ---- GRU pointwise (24 service threads); Hout + Hnew scatter inline --
        if (t2 >= 0 && t2 < 24) {
            const int d = t2;
            float rC = sigmf(S.giCs[d] + S.Gres[d]);
            float zC = sigmf(S.giCs[24 + d] + S.Gres[24 + d]);
            float nC = tanhf(S.giCs[48 + d] + rC * S.Gres[48 + d]);
            float Mv = S.Mfull[d0 + d];
            float Cc = (1.f - zC) * nC + zC * Mv;
            float rP = sigmf(S.Gres[72 + d] + S.ghPs[d]);
            float zP = sigmf(S.Gres[96 + d] + S.ghPs[24 + d]);
            float nP = tanhf(S.Gres[120 + d] + rP * S.ghPs[48 + d]);
            float hv = Cc + ((1.f - zP) * nP + zP * S.X24[d]);
            A.Hout[row * 576 + d0 + d] = hv;
            #pragma unroll
            for (int r = 0; r < 8; r++) st_remote(&S.Hnew[d0 + d], (unsigned)r, hv);
        }
        cluster_sync_all();   // Hnew assembled everywhere; anchors mbM phases
    }
}

// ------------------------------- launcher ------------------------------------
extern "C" void kernel_launch(void* const* d_in, const int* in_sizes, int n_in,
                              void* d_out, int out_size) {
    const float* features = (const float*)d_in[0];
    const float* adj      = (const float*)d_in[1];
    const float* smask    = (const float*)d_in[2];
    const float* fc1_w    = (const float*)d_in[5];
    const float* fc1_b    = (const float*)d_in[6];
    const float* gat_w    = (const float*)d_in[7];
    const float* wr0p     = (const float*)d_in[9];
    const float* wr1p     = (const float*)d_in[10];
    const float* gruc_wih = (const float*)d_in[11];
    const float* gruc_whh = (const float*)d_in[12];
    const float* gruc_bih = (const float*)d_in[13];
    const float* gruc_bhh = (const float*)d_in[14];
    const float* grup_wih = (const float*)d_in[15];
    const float* grup_whh = (const float*)d_in[16];
    const float* grup_bih = (const float*)d_in[17];
    const float* grup_bhh = (const float*)d_in[18];
    const float* mlp_w0   = (const float*)d_in[19];
    const float* mlp_b0   = (const float*)d_in[20];
    const float* mlp_w1   = (const float*)d_in[21];
    const float* mlp_b1   = (const float*)d_in[22];
    const float* mlp_w2   = (const float*)d_in[23];
    const float* mlp_b2   = (const float*)d_in[24];

    float* out = (float*)d_out;
    float* logits = out;                 // (8,256,192)
    float* attn = out + 8 * 256 * 192;   // (8,2,256,256)

    float *H, *GI, *GP, *T0, *T1;
    cudaGetSymbolAddress((void**)&H, g_H);
    cudaGetSymbolAddress((void**)&GI, g_giC);
    cudaGetSymbolAddress((void**)&GP, g_ghP);
    cudaGetSymbolAddress((void**)&T0, g_t0);
    cudaGetSymbolAddress((void**)&T1, g_t1);

    cudaFuncSetAttribute(scan_kernel, cudaFuncAttributeMaxDynamicSharedMemorySize,
                         (int)sizeof(SmemScan));

    dim3 blk(256);
    gemm_kernel<0, 1><<<dim3(3, 32), blk>>>(features, 768, fc1_w, fc1_b, H, 576,
                                            2048, 192, 768);
    for (int l = 0; l < 2; l++) {
        gemm_kernel<1, 0><<<dim3(9, 32), blk>>>(H + l * 192, 576,
                                                gruc_wih + l * 576 * 192,
                                                gruc_bih + l * 576, GI, 576,
                                                2048, 576, 192);
        gemm_kernel<1, 0><<<dim3(9, 32), blk>>>(H + l * 192, 576,
                                                grup_whh + l * 576 * 192,
                                                grup_bhh + l * 576, GP, 576,
                                                2048, 576, 192);
        ScanArgs SA;
        SA.Hl = H + l * 192;
        SA.adj = adj;
        SA.smask = smask;
        SA.wk = gat_w + l * 384 + 192;
        SA.wr0 = wr0p + l * 192 * 192;
        SA.wr1 = wr1p + l * 192 * 192;
        SA.whhC = gruc_whh + l * 576 * 192;
        SA.wihP = grup_wih + l * 576 * 192;
        SA.bhhC = gruc_bhh + l * 576;
        SA.biP = grup_bih + l * 576;
        SA.giC = GI;
        SA.ghP = GP;
        SA.Hout = H + (l + 1) * 192;
        SA.attnL = attn + l * 65536;
        scan_kernel<<<64, 512, sizeof(SmemScan)>>>(SA);
    }
    gemm_kernel<0, 1><<<dim3(3, 32), blk>>>(H, 576, mlp_w0, mlp_b0, T0, 192,
                                            2048, 192, 576);
    gemm_kernel<0, 1><<<dim3(3, 32), blk>>>(T0, 192, mlp_w1, mlp_b1, T1, 192,
                                            2048, 192, 192);
    gemm_kernel<0, 0><<<dim3(3, 32), blk>>>(T1, 192, mlp_w2, mlp_b2, logits, 192,
                                            2048, 192, 192);
}